// round 15
// baseline (speedup 1.0000x reference)
#include <cuda_runtime.h>
#include <cuda_fp16.h>
#include <stdint.h>

#define M_ROWS 8192
#define D_MODEL 768
#define N_LAT 16384
#define TOPK 32
#define NCAND 64

// GEMM tiling: 256 threads/CTA (8 warps of 64x32), 2 CTAs/SM, single-pass fp16
#define BM 128
#define BN 128
#define BK 32
#define KCHUNKS (D_MODEL / BK)       // 24
#define ROWB 80                       // padded row stride in bytes
#define ST_A  0
#define ST_B  (128 * ROWB)            // 10240
#define STAGE_B (2 * 128 * ROWB)      // 20480
#define NSTAGE 4
#define GEMM_SMEM (NSTAGE * STAGE_B)  // 81920 per CTA; 2 CTAs -> 160 KB

#define TPK_T 512                     // topk threads

// rerank chunking
#define RK_CH 128                     // k-elements per chunk
#define RK_NCH (D_MODEL / RK_CH)      // 6
#define RK_STRIDE 129                 // smem row stride (floats), conflict-free

// ---------------------------------------------------------------------------
// Device scratch
// ---------------------------------------------------------------------------
__device__ __align__(16) __half g_xh[(size_t)M_ROWS * D_MODEL];
__device__ __align__(16) __half g_wh[(size_t)N_LAT * D_MODEL];
__device__ float g_WdecT[(size_t)N_LAT * D_MODEL];
__device__ int   g_cand[(size_t)M_ROWS * NCAND];
__device__ int   g_tk_idx[(size_t)M_ROWS * TOPK];
__device__ float g_tk_val[(size_t)M_ROWS * TOPK];

// ---------------------------------------------------------------------------
// PTX helpers (baseline sm_80+ features only)
// ---------------------------------------------------------------------------
__device__ __forceinline__ uint32_t smem_u32(const void* p) {
    uint32_t a;
    asm("{ .reg .u64 t; cvta.to.shared.u64 t, %1; cvt.u32.u64 %0, t; }"
        : "=r"(a) : "l"(p));
    return a;
}
__device__ __forceinline__ void cp16(uint32_t dst, const void* src) {
    asm volatile("cp.async.cg.shared.global [%0], [%1], 16;"
                 :: "r"(dst), "l"(src) : "memory");
}
__device__ __forceinline__ void cp_commit() {
    asm volatile("cp.async.commit_group;" ::: "memory");
}
template <int N>
__device__ __forceinline__ void cp_wait() {
    asm volatile("cp.async.wait_group %0;" :: "n"(N) : "memory");
}
__device__ __forceinline__ void ldsm4(uint32_t* r, uint32_t addr) {
    asm volatile("ldmatrix.sync.aligned.m8n8.x4.shared.b16 {%0,%1,%2,%3}, [%4];"
                 : "=r"(r[0]), "=r"(r[1]), "=r"(r[2]), "=r"(r[3]) : "r"(addr));
}
__device__ __forceinline__ void mma16816(float* c, const uint32_t* a, const uint32_t* b) {
    asm volatile(
        "mma.sync.aligned.m16n8k16.row.col.f32.f16.f16.f32 "
        "{%0,%1,%2,%3}, {%4,%5,%6,%7}, {%8,%9}, {%0,%1,%2,%3};"
        : "+f"(c[0]), "+f"(c[1]), "+f"(c[2]), "+f"(c[3])
        : "r"(a[0]), "r"(a[1]), "r"(a[2]), "r"(a[3]), "r"(b[0]), "r"(b[1]));
}
__device__ __forceinline__ unsigned short key16(float v) {
    unsigned u = __float_as_uint(v);
    unsigned m = (u & 0x80000000u) ? ~u : (u | 0x80000000u);
    return (unsigned short)(m >> 16);
}

// ---------------------------------------------------------------------------
// Kernels: fp16 conversions
// ---------------------------------------------------------------------------
__global__ void conv_x_kernel(const float* __restrict__ src, int n)
{
    int i = blockIdx.x * blockDim.x + threadIdx.x;
    if (i < n) g_xh[i] = __float2half_rn(src[i]);
}
__global__ void conv_w_kernel(const float* __restrict__ src, int n)
{
    int i = blockIdx.x * blockDim.x + threadIdx.x;
    if (i < n) g_wh[i] = __float2half_rn(src[i]);
}

// ---------------------------------------------------------------------------
// Kernel: encoder GEMM, single-pass fp16 mma.sync (unchanged from R11/R12).
// ---------------------------------------------------------------------------
__global__ void __launch_bounds__(256, 2) gemm_enc_mma(
    const float* __restrict__ bias, float* __restrict__ C)
{
    extern __shared__ char smp[];
    const uint32_t sb = smem_u32(smp);
    __shared__ float sBias[BN];

    const int tid  = threadIdx.x;
    const int wid  = tid >> 5;
    const int lane = tid & 31;
    const int wm   = wid & 1;
    const int wn   = wid >> 1;
    const int bm   = blockIdx.y * BM;
    const int bn   = blockIdx.x * BN;

    if (tid < BN) sBias[tid] = bias[bn + tid];

    const int q  = lane >> 3;
    const int lr = lane & 7;
    int rbA[4];
    #pragma unroll
    for (int i = 0; i < 4; ++i)
        rbA[i] = (wm * 64 + i * 16 + (q & 1) * 8 + lr) * ROWB + (q >> 1) * 16;
    int rbB[2];
    #pragma unroll
    for (int p = 0; p < 2; ++p)
        rbB[p] = (wn * 32 + (2 * p + (lane >> 4)) * 8 + lr) * ROWB + ((lane >> 3) & 1) * 16;

    float acc[4][4][4];
    #pragma unroll
    for (int i = 0; i < 4; ++i)
        #pragma unroll
        for (int j = 0; j < 4; ++j)
            #pragma unroll
            for (int k = 0; k < 4; ++k)
                acc[i][j][k] = 0.0f;

    auto cp_chunk = [&](int c, int st) {
        const int kt = c * BK;
        const uint32_t base = sb + st * STAGE_B;
        #pragma unroll
        for (int i = 0; i < 4; ++i) {
            const int u   = tid + 256 * i;
            const int seg = u & 3;
            const int r   = u >> 2;
            if (r < 128) {
                cp16(base + ST_A + r * ROWB + seg * 16,
                     g_xh + (size_t)(bm + r) * D_MODEL + kt + seg * 8);
            } else {
                const int rr = r - 128;
                cp16(base + ST_B + rr * ROWB + seg * 16,
                     g_wh + (size_t)(bn + rr) * D_MODEL + kt + seg * 8);
            }
        }
        cp_commit();
    };

    cp_chunk(0, 0);
    cp_chunk(1, 1);
    cp_chunk(2, 2);

    for (int c = 0; c < KCHUNKS; ++c) {
        if (c <= KCHUNKS - 3)      cp_wait<2>();
        else if (c == KCHUNKS - 2) cp_wait<1>();
        else                       cp_wait<0>();
        __syncthreads();
        if (c + 3 < KCHUNKS) cp_chunk(c + 3, (c + 3) % NSTAGE);

        const uint32_t base = sb + (c % NSTAGE) * STAGE_B;
        #pragma unroll
        for (int s = 0; s < 2; ++s) {
            const int so = s * 32;
            uint32_t af[4][4], br[4][2];
            #pragma unroll
            for (int i = 0; i < 4; ++i) ldsm4(af[i], base + ST_A + rbA[i] + so);
            #pragma unroll
            for (int p = 0; p < 2; ++p) {
                uint32_t t[4];
                ldsm4(t, base + ST_B + rbB[p] + so);
                br[2*p][0] = t[0]; br[2*p][1] = t[1];
                br[2*p+1][0] = t[2]; br[2*p+1][1] = t[3];
            }
            #pragma unroll
            for (int i = 0; i < 4; ++i)
                #pragma unroll
                for (int j = 0; j < 4; ++j) mma16816(acc[i][j], af[i], br[j]);
        }
        __syncthreads();
    }

    const int er = lane >> 2;
    const int ec = (lane & 3) * 2;
    #pragma unroll
    for (int i = 0; i < 4; ++i) {
        const int row = bm + wm * 64 + i * 16 + er;
        float* crow0 = C + (size_t)row * N_LAT + bn + wn * 32;
        float* crow1 = crow0 + (size_t)8 * N_LAT;
        #pragma unroll
        for (int j = 0; j < 4; ++j) {
            const int colb = j * 8 + ec;
            const float bz0 = sBias[wn * 32 + colb];
            const float bz1 = sBias[wn * 32 + colb + 1];
            float2 v0 = make_float2(acc[i][j][0] + bz0, acc[i][j][1] + bz1);
            float2 v1 = make_float2(acc[i][j][2] + bz0, acc[i][j][3] + bz1);
            *(float2*)(crow0 + colb) = v0;
            *(float2*)(crow1 + colb) = v1;
        }
    }
}

// ---------------------------------------------------------------------------
// Kernel: W_dec [D_MODEL, N_LAT] -> g_WdecT [N_LAT, D_MODEL]
// ---------------------------------------------------------------------------
__global__ void transpose_kernel(const float* __restrict__ Wdec)
{
    __shared__ float tile[32][33];
    const int l  = blockIdx.x * 32 + threadIdx.x;
    const int d0 = blockIdx.y * 32;
    #pragma unroll
    for (int j = threadIdx.y; j < 32; j += 8)
        tile[j][threadIdx.x] = Wdec[(size_t)(d0 + j) * N_LAT + l];
    __syncthreads();
    const int d  = d0 + threadIdx.x;
    const int l0 = blockIdx.x * 32;
    #pragma unroll
    for (int j = threadIdx.y; j < 32; j += 8)
        g_WdecT[(size_t)(l0 + j) * D_MODEL + d] = tile[threadIdx.x][j];
}

// ---------------------------------------------------------------------------
// Kernel: top-NCAND candidates per row (unchanged from R12).
// ---------------------------------------------------------------------------
__global__ void __launch_bounds__(TPK_T) topk_kernel(
    const float* __restrict__ pre, float* __restrict__ latents)
{
    __shared__ __align__(16) unsigned short skey[N_LAT];   // 32 KB
    __shared__ unsigned hist[256];
    __shared__ unsigned suff[257];
    __shared__ unsigned s_b, s_remk;
    __shared__ unsigned wcnt_g[16], wcnt_e[16];

    const int row = blockIdx.x;
    const int tid = threadIdx.x;
    const int wrp = tid >> 5;
    const int lid = tid & 31;

    const float4* prow4 = (const float4*)(pre + (size_t)row * N_LAT);
    float4*       lat4  = (float4*)(latents + (size_t)row * N_LAT);

    if (tid < 256) hist[tid] = 0u;

    const float4 z4 = make_float4(0.f, 0.f, 0.f, 0.f);
    #pragma unroll
    for (int j = 0; j < 8; ++j) {
        const int i4 = tid + TPK_T * j;
        float4 v = prow4[i4];
        lat4[i4] = z4;
        ushort4 kk;
        kk.x = key16(v.x); kk.y = key16(v.y);
        kk.z = key16(v.z); kk.w = key16(v.w);
        ((ushort4*)skey)[i4] = kk;
    }
    __syncthreads();

    #pragma unroll 4
    for (int j = 0; j < 32; ++j) {
        const unsigned b = (unsigned)(skey[tid + TPK_T * j]) >> 8;
        const unsigned peers = __match_any_sync(0xFFFFFFFFu, b);
        if ((peers & ((1u << lid) - 1u)) == 0u)
            atomicAdd(&hist[b], __popc(peers));
    }
    __syncthreads();

    unsigned remk = NCAND;
    if (tid < 256) suff[tid] = hist[tid];
    if (tid == 0) suff[256] = 0u;
    __syncthreads();
    #pragma unroll
    for (int st = 1; st < 256; st <<= 1) {
        unsigned add = (tid < 256 && tid + st < 256) ? suff[tid + st] : 0u;
        __syncthreads();
        if (tid < 256) suff[tid] += add;
        __syncthreads();
    }
    if (tid < 256 && suff[tid] >= remk && suff[tid + 1] < remk) {
        s_b = (unsigned)tid;
        s_remk = remk - suff[tid + 1];
    }
    __syncthreads();
    const unsigned p8 = s_b;
    remk = s_remk;
    __syncthreads();

    if (tid < 256) hist[tid] = 0u;
    __syncthreads();
    for (int j = 0; j < 32; ++j) {
        const unsigned k = (unsigned)skey[tid + TPK_T * j];
        const bool act = ((k >> 8) == p8);
        const unsigned amask = __ballot_sync(0xFFFFFFFFu, act);
        if (act) {
            const unsigned b = k & 0xFFu;
            const unsigned peers = __match_any_sync(amask, b);
            if ((peers & ((1u << lid) - 1u)) == 0u)
                atomicAdd(&hist[b], __popc(peers));
        }
    }
    __syncthreads();
    if (tid < 256) suff[tid] = hist[tid];
    if (tid == 0) suff[256] = 0u;
    __syncthreads();
    #pragma unroll
    for (int st = 1; st < 256; st <<= 1) {
        unsigned add = (tid < 256 && tid + st < 256) ? suff[tid + st] : 0u;
        __syncthreads();
        if (tid < 256) suff[tid] += add;
        __syncthreads();
    }
    if (tid < 256 && suff[tid] >= remk && suff[tid + 1] < remk) {
        s_b = (unsigned)tid;
        s_remk = remk - suff[tid + 1];
    }
    __syncthreads();
    const unsigned T16 = (p8 << 8) | s_b;
    remk = s_remk;
    __syncthreads();

    const int seg0 = wrp * 1024;
    unsigned ng = 0, ne = 0;
    for (int base = seg0; base < seg0 + 1024; base += 32) {
        const unsigned k = (unsigned)skey[base + lid];
        ng += __popc(__ballot_sync(0xFFFFFFFFu, k > T16));
        ne += __popc(__ballot_sync(0xFFFFFFFFu, k == T16));
    }
    if (lid == 0) { wcnt_g[wrp] = ng; wcnt_e[wrp] = ne; }
    __syncthreads();
    unsigned gt_total = 0, gbase = 0, ebase = 0;
    #pragma unroll
    for (int w = 0; w < 16; ++w) {
        if (w < wrp) { gbase += wcnt_g[w]; ebase += wcnt_e[w]; }
        gt_total += wcnt_g[w];
    }
    const unsigned lmask = (1u << lid) - 1u;
    unsigned gofs = gbase, eofs = ebase;
    for (int base = seg0; base < seg0 + 1024; base += 32) {
        const unsigned k = (unsigned)skey[base + lid];
        const bool gt = (k > T16);
        const bool eq = (k == T16);
        const unsigned bg = __ballot_sync(0xFFFFFFFFu, gt);
        const unsigned be = __ballot_sync(0xFFFFFFFFu, eq);
        int slot = -1;
        if (gt) {
            slot = (int)(gofs + __popc(bg & lmask));
        } else if (eq) {
            const unsigned ger = eofs + __popc(be & lmask);
            if (ger < remk) slot = (int)(gt_total + ger);
        }
        if (slot >= 0 && slot < NCAND)
            g_cand[(size_t)row * NCAND + slot] = base + lid;
        gofs += __popc(bg);
        eofs += __popc(be);
    }
}

// ---------------------------------------------------------------------------
// Kernel: exact fp32 re-rank. Same strictly-sequential k=0..767 fmaf chain
// per candidate (bit-identical arithmetic), but W rows staged through smem
// in coalesced K-chunks — kills the 32-way divergent-LDG wavefront storm.
// ---------------------------------------------------------------------------
__global__ void __launch_bounds__(NCAND) rerank_kernel(
    const float* __restrict__ x, const float* __restrict__ W_enc,
    const float* __restrict__ b_enc, float* __restrict__ latents)
{
    __shared__ float sx[D_MODEL];
    __shared__ float sw[NCAND * RK_STRIDE];   // 64 rows x chunk of 128 (stride 129)
    __shared__ float sval[NCAND];
    __shared__ int   sidx[NCAND];

    const int row = blockIdx.x;
    const int tid = threadIdx.x;

    #pragma unroll
    for (int i = tid; i < D_MODEL; i += NCAND)
        sx[i] = x[(size_t)row * D_MODEL + i];
    sidx[tid] = g_cand[(size_t)row * NCAND + tid];
    __syncthreads();

    const float* __restrict__ wrow_own = W_enc + (size_t)sidx[tid] * D_MODEL;
    float acc = 0.0f;

    #pragma unroll
    for (int c = 0; c < RK_NCH; ++c) {
        const int k0 = c * RK_CH;
        __syncthreads();   // previous chunk's consumers done
        // cooperative coalesced load: 64x128 elements; warp reads 32
        // consecutive floats of one row per step.
        #pragma unroll
        for (int it = 0; it < (NCAND * RK_CH) / NCAND; ++it) {
            const int u = tid + NCAND * it;
            const int r = u >> 7;            // candidate row
            const int k = u & (RK_CH - 1);   // k within chunk
            sw[r * RK_STRIDE + k] =
                __ldg(W_enc + (size_t)sidx[r] * D_MODEL + k0 + k);
        }
        __syncthreads();
        // sequential chain over this chunk (order preserved globally)
        const float* wr = sw + tid * RK_STRIDE;
        #pragma unroll 16
        for (int k = 0; k < RK_CH; ++k)
            acc = fmaf(sx[k0 + k], wr[k], acc);
    }
    (void)wrow_own;

    sval[tid] = acc + b_enc[sidx[tid]];
    __syncthreads();

    const float v = sval[tid];
    const int idx = sidx[tid];
    int rank = 0;
    #pragma unroll
    for (int j = 0; j < NCAND; ++j) {
        const float vj = sval[j];
        rank += (vj > v) || (vj == v && sidx[j] < idx);
    }
    if (rank < TOPK) {
        const float rv = fmaxf(v, 0.0f);
        g_tk_idx[(size_t)row * TOPK + rank] = idx;
        g_tk_val[(size_t)row * TOPK + rank] = rv;
        latents[(size_t)row * N_LAT + idx] = rv;
    }
}

// ---------------------------------------------------------------------------
// Kernel: sparse decode
// ---------------------------------------------------------------------------
__global__ void __launch_bounds__(256) decode_kernel(
    const float* __restrict__ b_dec, float* __restrict__ rec)
{
    const int row = blockIdx.x;
    __shared__ int   sidx[TOPK];
    __shared__ float sval[TOPK];
    const int tid = threadIdx.x;
    if (tid < TOPK) {
        sidx[tid] = g_tk_idx[(size_t)row * TOPK + tid];
        sval[tid] = g_tk_val[(size_t)row * TOPK + tid];
    }
    __syncthreads();
    for (int d = tid; d < D_MODEL; d += 256) {
        float acc = b_dec[d];
        #pragma unroll
        for (int j = 0; j < TOPK; ++j)
            acc = fmaf(sval[j], g_WdecT[(size_t)sidx[j] * D_MODEL + d], acc);
        rec[(size_t)row * D_MODEL + d] = acc;
    }
}

// ---------------------------------------------------------------------------
// Launch
// ---------------------------------------------------------------------------
extern "C" void kernel_launch(void* const* d_in, const int* in_sizes, int n_in,
                              void* d_out, int out_size)
{
    const float* x     = (const float*)d_in[0];
    const float* W_enc = (const float*)d_in[1];
    const float* b_enc = (const float*)d_in[2];
    const float* W_dec = (const float*)d_in[3];
    const float* b_dec = (const float*)d_in[4];

    float* out = (float*)d_out;
    const size_t LAT_ELEMS = (size_t)M_ROWS * N_LAT;
    const size_t REC_ELEMS = (size_t)M_ROWS * D_MODEL;
    float* latents = out;
    float* rec     = out + LAT_ELEMS;
    float* pre     = out + LAT_ELEMS + REC_ELEMS;

    cudaFuncSetAttribute(gemm_enc_mma, cudaFuncAttributeMaxDynamicSharedMemorySize, GEMM_SMEM);

    const int n_x = M_ROWS * D_MODEL;
    const int n_w = N_LAT * D_MODEL;
    conv_x_kernel<<<(n_x + 255) / 256, 256>>>(x, n_x);           // 1
    conv_w_kernel<<<(n_w + 255) / 256, 256>>>(W_enc, n_w);       // 2

    transpose_kernel<<<dim3(N_LAT / 32, D_MODEL / 32), dim3(32, 8)>>>(W_dec);  // 3

    gemm_enc_mma<<<dim3(N_LAT / BN, M_ROWS / BM), 256, GEMM_SMEM>>>(b_enc, pre); // 4

    topk_kernel<<<M_ROWS, TPK_T>>>(pre, latents);                // 5 (zeroes latents too)

    rerank_kernel<<<M_ROWS, NCAND>>>(x, W_enc, b_enc, latents);  // 6

    decode_kernel<<<M_ROWS, 256>>>(b_dec, rec);                  // 7
}